// round 8
// baseline (speedup 1.0000x reference)
#include <cuda_runtime.h>
#include <math.h>

#define BB   2
#define TT   2048
#define HID  1024
#define HH   16
#define HKV  4
#define MROWS  (BB*TT)          // 4096
#define QCOLS  1024
#define KVCOLS 512
#define NCHUNK 32               // T / 64

// ---------------- scratch (device globals; no allocation) ------------------
__device__ float g_hst[MROWS * HID];       // hs rounded to tf32
__device__ float g_q[MROWS * QCOLS];       // relu(hs@Wq)
__device__ float g_kv[MROWS * KVCOLS];     // [relu(hs@Wk)->ke | hs@Wv]
__device__ float g_lg[MROWS * 256];        // log decay -> then be=exp(b)*0.125
__device__ float g_oattn[MROWS * QCOLS];   // normed attention out (tf32-rounded)
__device__ float g_Wkv[HID * KVCOLS];      // concat(Wk, Wv), tf32-rounded
__device__ float g_Wq[HID * QCOLS];        // Wq tf32-rounded
__device__ float g_Wo[QCOLS * HID];        // Wo tf32-rounded
__device__ float g_S[8 * NCHUNK * 64 * 64];// per-chunk entering states
__device__ float g_dl[8 * NCHUNK * 64];    // exp(b_last)

// ---------------- tf32 mma helpers -----------------------------------------
__device__ __forceinline__ unsigned f2tf(float x) {
    unsigned r; asm("cvt.rna.tf32.f32 %0, %1;" : "=r"(r) : "f"(x)); return r;
}
__device__ __forceinline__ float f2tff(float x) {
    return __uint_as_float(f2tf(x));
}
__device__ __forceinline__ void mma_tf32(float* c, const unsigned* a,
                                         unsigned b0, unsigned b1) {
    asm volatile(
        "mma.sync.aligned.m16n8k8.row.col.f32.tf32.tf32.f32 "
        "{%0,%1,%2,%3},{%4,%5,%6,%7},{%8,%9},{%0,%1,%2,%3};"
        : "+f"(c[0]), "+f"(c[1]), "+f"(c[2]), "+f"(c[3])
        : "r"(a[0]), "r"(a[1]), "r"(a[2]), "r"(a[3]), "r"(b0), "r"(b1));
}
__device__ __forceinline__ void cp16(void* smem, const void* g) {
    unsigned s = (unsigned)__cvta_generic_to_shared(smem);
    asm volatile("cp.async.cg.shared.global [%0], [%1], 16;" :: "r"(s), "l"(g) : "memory");
}
__device__ __forceinline__ void cp_commit() {
    asm volatile("cp.async.commit_group;" ::: "memory");
}

// ---------------- cp.async tf32 GEMM: C = act(A @ B), inputs pre-rounded ---
// BM=128, BN=128, BK=32, 3-stage cp.async ring, 256 threads (8 warps 4x2).
#define GLDA 36
#define GLDB 136
#define GSMEM_WORDS (3 * (128 * GLDA + 32 * GLDB))

__global__ void __launch_bounds__(256, 2) mma_gemm(const float* __restrict__ A,
                                                   const float* __restrict__ B,
                                                   float* __restrict__ C,
                                                   int M, int N, int K,
                                                   int relu_limit) {
    extern __shared__ unsigned sm[];
    unsigned (*As)[128][GLDA] = (unsigned(*)[128][GLDA])sm;
    unsigned (*Bs)[32][GLDB]  = (unsigned(*)[32][GLDB])(sm + 3 * 128 * GLDA);

    const int tid  = threadIdx.x;
    const int lane = tid & 31;
    const int warp = tid >> 5;
    const int row0 = blockIdx.y * 128;
    const int col0 = blockIdx.x * 128;
    const int wm = (warp & 3) * 32;
    const int wn = (warp >> 2) * 64;
    const int gr = lane >> 2, gc = lane & 3;

    float acc[2][8][4];
    #pragma unroll
    for (int i = 0; i < 2; i++)
        #pragma unroll
        for (int j = 0; j < 8; j++)
            #pragma unroll
            for (int l = 0; l < 4; l++) acc[i][j][l] = 0.f;

    auto CPA = [&](int kt, int st) {
        const float* ab = A + (size_t)row0 * K + kt * 32;
        #pragma unroll
        for (int i = 0; i < 4; i++) {
            int ch = tid + i * 256;          // 1024 chunks: 128 rows x 8 float4
            int r = ch >> 3, cc = (ch & 7) * 4;
            cp16(&As[st][r][cc], ab + (size_t)r * K + cc);
        }
        const float* bb = B + (size_t)kt * 32 * N + col0;
        #pragma unroll
        for (int i = 0; i < 4; i++) {
            int ch = tid + i * 256;          // 1024 chunks: 32 k x 32 float4
            int kk = ch >> 5, nn = (ch & 31) * 4;
            cp16(&Bs[st][kk][nn], bb + (size_t)kk * N + nn);
        }
        cp_commit();
    };

    auto COMP = [&](int st) {
        #pragma unroll
        for (int ks = 0; ks < 4; ks++) {
            int cb = ks * 8 + gc;
            unsigned a[2][4];
            #pragma unroll
            for (int mt = 0; mt < 2; mt++) {
                int r = wm + mt * 16 + gr;
                a[mt][0] = As[st][r][cb];
                a[mt][1] = As[st][r + 8][cb];
                a[mt][2] = As[st][r][cb + 4];
                a[mt][3] = As[st][r + 8][cb + 4];
            }
            #pragma unroll
            for (int nt = 0; nt < 8; nt++) {
                int nc = wn + nt * 8 + gr;
                unsigned b0 = Bs[st][cb][nc];
                unsigned b1 = Bs[st][cb + 4][nc];
                mma_tf32(acc[0][nt], a[0], b0, b1);
                mma_tf32(acc[1][nt], a[1], b0, b1);
            }
        }
    };

    const int NT = K / 32;
    CPA(0, 0); CPA(1, 1);
    for (int kt = 0; kt < NT; kt++) {
        if (kt + 1 < NT) {
            asm volatile("cp.async.wait_group 1;" ::: "memory");
        } else {
            asm volatile("cp.async.wait_group 0;" ::: "memory");
        }
        __syncthreads();
        if (kt + 2 < NT) CPA(kt + 2, (kt + 2) % 3);
        COMP(kt % 3);
    }

    #pragma unroll
    for (int mt = 0; mt < 2; mt++) {
        #pragma unroll
        for (int nt = 0; nt < 8; nt++) {
            int r  = row0 + wm + mt * 16 + gr;
            int cc = col0 + wn + nt * 8 + gc * 2;
            float v0 = acc[mt][nt][0], v1 = acc[mt][nt][1];
            float v2 = acc[mt][nt][2], v3 = acc[mt][nt][3];
            if (cc < relu_limit) {
                v0 = fmaxf(v0, 0.f); v1 = fmaxf(v1, 0.f);
                v2 = fmaxf(v2, 0.f); v3 = fmaxf(v3, 0.f);
            }
            *(float2*)&C[(size_t)r * N + cc]       = make_float2(v0, v1);
            *(float2*)&C[(size_t)(r + 8) * N + cc] = make_float2(v2, v3);
        }
    }
}

// ---------------- prep: round weights/activations to tf32 ------------------
__global__ void prep_w(const float* __restrict__ Wq, const float* __restrict__ Wk,
                       const float* __restrict__ Wv, const float* __restrict__ Wo) {
    int i = blockIdx.x * 256 + threadIdx.x;   // over 1M
    g_Wq[i] = f2tff(Wq[i]);
    g_Wo[i] = f2tff(Wo[i]);
    if (i < HID * KVCOLS) {
        int k = i >> 9, n = i & 511;
        g_Wkv[i] = f2tff((n < 256) ? Wk[k * 256 + n] : Wv[k * 256 + n - 256]);
    }
}
__global__ void conv_hs(const float* __restrict__ hs) {
    int i = blockIdx.x * 256 + threadIdx.x;   // over 1M float4
    float4 v = ((const float4*)hs)[i];
    ((float4*)g_hst)[i] = make_float4(f2tff(v.x), f2tff(v.y), f2tff(v.z), f2tff(v.w));
}

// ---------------- fused gate: lg = logsigmoid((hs@Wg1)@Wg2 + b)/16 ---------
// 128 blocks x 32 rows, 256 threads. Wg1/Wg2 tiles staged in smem.
__global__ void __launch_bounds__(256) gate_fused(const float* __restrict__ hs,
                                                  const float* __restrict__ Wg1,
                                                  const float* __restrict__ Wg2,
                                                  const float* __restrict__ bg2) {
    __shared__ float hs_s[32][128];
    __shared__ float w1_s[128][16];
    __shared__ float glow_s[32][16];
    __shared__ float w2_s[16][256];

    const int tid = threadIdx.x;
    const int row0 = blockIdx.x * 32;
    const int rowA = tid >> 4;      // 0..15 -> rows rowA, rowA+16
    const int col  = tid & 15;

    #pragma unroll
    for (int i = tid; i < 4096; i += 256)
        w2_s[i >> 8][i & 255] = Wg2[i];

    float acc0 = 0.f, acc1 = 0.f;
    for (int kt = 0; kt < 8; kt++) {
        __syncthreads();
        // 32 rows x 128 cols = 1024 float4, 32 float4 per row
        #pragma unroll
        for (int i = 0; i < 4; i++) {
            int ch = tid + i * 256;
            int r = ch >> 5, cc = (ch & 31) * 4;
            *(float4*)&hs_s[r][cc] = *(const float4*)&hs[(size_t)(row0 + r) * HID + kt * 128 + cc];
        }
        // 128 k x 16 cols = 512 float4, 4 float4 per row
        #pragma unroll
        for (int i = 0; i < 2; i++) {
            int ch = tid + i * 256;
            int kk = ch >> 2, cc = (ch & 3) * 4;
            *(float4*)&w1_s[kk][cc] = *(const float4*)&Wg1[(size_t)(kt * 128 + kk) * 16 + cc];
        }
        __syncthreads();
        #pragma unroll 8
        for (int k = 0; k < 128; k++) {
            float w = w1_s[k][col];
            acc0 = fmaf(hs_s[rowA][k], w, acc0);
            acc1 = fmaf(hs_s[rowA + 16][k], w, acc1);
        }
    }
    glow_s[rowA][col]      = acc0;
    glow_s[rowA + 16][col] = acc1;
    __syncthreads();

    const int c = tid;
    const float bias = bg2[c];
    #pragma unroll 4
    for (int r = 0; r < 32; r++) {
        float x = bias;
        #pragma unroll
        for (int j = 0; j < 16; j++) x = fmaf(glow_s[r][j], w2_s[j][c], x);
        float ls = fminf(x, 0.f) - log1pf(__expf(-fabsf(x)));
        g_lg[(size_t)(row0 + r) * 256 + c] = ls * 0.0625f;
    }
}

// ---------------- Phase A: cumsum; be=exp(b)/8 in place; scale k -----------
__global__ void __launch_bounds__(64) phaseA_kernel() {
    const int c   = blockIdx.x & 31;
    const int grp = blockIdx.x >> 5;
    const int b = grp >> 2, hk = grp & 3;
    const int d = threadIdx.x;
    float bacc = 0.f;
    const size_t row0 = (size_t)b * TT + c * 64;
    for (int t = 0; t < 64; t++) {
        const size_t r = row0 + t;
        bacc += g_lg[r * 256 + hk * 64 + d];
        g_lg[r * 256 + hk * 64 + d] = __expf(bacc) * 0.125f;
        g_kv[r * 512 + hk * 64 + d] *= __expf(-bacc);
    }
    g_dl[(grp * 32 + c) * 64 + d] = __expf(bacc);
}

// ---------------- Phase B: propagate states across chunks ------------------
__global__ void __launch_bounds__(128) phaseB_kernel() {
    const int grp = blockIdx.x >> 3;
    const int vc  = blockIdx.x & 7;
    const int b = grp >> 2, hk = grp & 3;
    const int tid = threadIdx.x;
    const int v  = tid & 7;
    const int kg = tid >> 3;
    __shared__ float ke_s[64][64];
    __shared__ float v_s[64][8];
    float S0 = 0.f, S1 = 0.f, S2 = 0.f, S3 = 0.f;

    for (int c = 0; c < NCHUNK; c++) {
        const size_t row0 = (size_t)b * TT + c * 64;
        __syncthreads();
        #pragma unroll
        for (int i = tid; i < 64 * 16; i += 128) {
            int t = i >> 4, dq = i & 15;
            ((float4*)ke_s[t])[dq] = *(const float4*)&g_kv[(row0 + t) * 512 + hk * 64 + dq * 4];
        }
        {
            int t = tid >> 1, q4 = tid & 1;
            ((float4*)v_s[t])[q4] = *(const float4*)&g_kv[(row0 + t) * 512 + 256 + hk * 64 + vc * 8 + q4 * 4];
        }
        __syncthreads();

        const size_t sb_ = ((size_t)(grp * 32 + c) * 64 + kg * 4) * 64 + vc * 8 + v;
        g_S[sb_]       = S0;
        g_S[sb_ + 64]  = S1;
        g_S[sb_ + 128] = S2;
        g_S[sb_ + 192] = S3;

        #pragma unroll 4
        for (int t = 0; t < 64; t++) {
            const float4 kk = ((const float4*)ke_s[t])[kg];
            const float  vv = v_s[t][v];
            S0 = fmaf(kk.x, vv, S0);
            S1 = fmaf(kk.y, vv, S1);
            S2 = fmaf(kk.z, vv, S2);
            S3 = fmaf(kk.w, vv, S3);
        }
        const float4 dl4 = *(const float4*)&g_dl[(grp * 32 + c) * 64 + kg * 4];
        S0 *= dl4.x; S1 *= dl4.y; S2 *= dl4.z; S3 *= dl4.w;
    }
}

// ---------------- Phase C: tensor-core intra-chunk + inter + RMSNorm -------
#define PC_LD 65
__global__ void __launch_bounds__(256) phaseC_kernel(const float* __restrict__ gnw) {
    extern __shared__ unsigned smc[];
    unsigned* qe  = smc;
    unsigned* keT = smc + 64 * PC_LD;
    unsigned* vs  = smc + 2 * 64 * PC_LD;
    unsigned* Ss  = smc + 3 * 64 * PC_LD;
    __shared__ float rs[64][2];

    const int c   = blockIdx.x & 31;
    const int h   = (blockIdx.x >> 5) & 3;
    const int grp = blockIdx.x >> 7;
    const int b = grp >> 2, hk = grp & 3;
    const int tid  = threadIdx.x;
    const int lane = tid & 31;
    const int warp = tid >> 5;
    const int wm = (warp & 3) * 16;
    const int wn = (warp >> 2) * 32;
    const int gr = lane >> 2, gc = lane & 3;
    const size_t row0 = (size_t)b * TT + c * 64;

    for (int i = tid; i < 4096; i += 256) {
        int t = i >> 6, d = i & 63;
        float qv = g_q[(row0 + t) * 1024 + hk * 256 + h * 64 + d]
                 * g_lg[(row0 + t) * 256 + hk * 64 + d];
        qe [t * PC_LD + d] = f2tf(qv);
        keT[d * PC_LD + t] = f2tf(g_kv[(row0 + t) * 512 + hk * 64 + d]);
        vs [t * PC_LD + d] = f2tf(g_kv[(row0 + t) * 512 + 256 + hk * 64 + d]);
        Ss [t * PC_LD + d] = f2tf(g_S[((size_t)(grp * 32 + c) * 64 + t) * 64 + d]);
    }
    __syncthreads();

    float accA[4][4];
    #pragma unroll
    for (int j = 0; j < 4; j++)
        #pragma unroll
        for (int l = 0; l < 4; l++) accA[j][l] = 0.f;
    const int rm = wm + gr;
    #pragma unroll
    for (int ks = 0; ks < 8; ks++) {
        int cb = ks * 8 + gc;
        unsigned a[4];
        a[0] = qe[rm * PC_LD + cb];
        a[1] = qe[(rm + 8) * PC_LD + cb];
        a[2] = qe[rm * PC_LD + cb + 4];
        a[3] = qe[(rm + 8) * PC_LD + cb + 4];
        #pragma unroll
        for (int nt = 0; nt < 4; nt++) {
            int nc = wn + nt * 8 + gr;
            unsigned b0 = keT[cb * PC_LD + nc];
            unsigned b1 = keT[(cb + 4) * PC_LD + nc];
            mma_tf32(accA[nt], a, b0, b1);
        }
    }
    __syncthreads();
    #pragma unroll
    for (int nt = 0; nt < 4; nt++) {
        int s0 = wn + nt * 8 + gc * 2;
        keT[rm * PC_LD + s0]           = f2tf(s0     <= rm     ? accA[nt][0] : 0.f);
        keT[rm * PC_LD + s0 + 1]       = f2tf(s0 + 1 <= rm     ? accA[nt][1] : 0.f);
        keT[(rm + 8) * PC_LD + s0]     = f2tf(s0     <= rm + 8 ? accA[nt][2] : 0.f);
        keT[(rm + 8) * PC_LD + s0 + 1] = f2tf(s0 + 1 <= rm + 8 ? accA[nt][3] : 0.f);
    }
    __syncthreads();

    float acc[4][4];
    #pragma unroll
    for (int j = 0; j < 4; j++)
        #pragma unroll
        for (int l = 0; l < 4; l++) acc[j][l] = 0.f;
    #pragma unroll
    for (int ks = 0; ks < 8; ks++) {
        int cb = ks * 8 + gc;
        unsigned a[4];
        a[0] = keT[rm * PC_LD + cb];
        a[1] = keT[(rm + 8) * PC_LD + cb];
        a[2] = keT[rm * PC_LD + cb + 4];
        a[3] = keT[(rm + 8) * PC_LD + cb + 4];
        #pragma unroll
        for (int nt = 0; nt < 4; nt++) {
            int nc = wn + nt * 8 + gr;
            unsigned b0 = vs[cb * PC_LD + nc];
            unsigned b1 = vs[(cb + 4) * PC_LD + nc];
            mma_tf32(acc[nt], a, b0, b1);
        }
    }
    #pragma unroll
    for (int ks = 0; ks < 8; ks++) {
        int cb = ks * 8 + gc;
        unsigned a[4];
        a[0] = qe[rm * PC_LD + cb];
        a[1] = qe[(rm + 8) * PC_LD + cb];
        a[2] = qe[rm * PC_LD + cb + 4];
        a[3] = qe[(rm + 8) * PC_LD + cb + 4];
        #pragma unroll
        for (int nt = 0; nt < 4; nt++) {
            int nc = wn + nt * 8 + gr;
            unsigned b0 = Ss[cb * PC_LD + nc];
            unsigned b1 = Ss[(cb + 4) * PC_LD + nc];
            mma_tf32(acc[nt], a, b0, b1);
        }
    }

    float ss0 = 0.f, ss1 = 0.f;
    #pragma unroll
    for (int nt = 0; nt < 4; nt++) {
        ss0 += acc[nt][0] * acc[nt][0] + acc[nt][1] * acc[nt][1];
        ss1 += acc[nt][2] * acc[nt][2] + acc[nt][3] * acc[nt][3];
    }
    ss0 += __shfl_xor_sync(0xffffffffu, ss0, 1);
    ss0 += __shfl_xor_sync(0xffffffffu, ss0, 2);
    ss1 += __shfl_xor_sync(0xffffffffu, ss1, 1);
    ss1 += __shfl_xor_sync(0xffffffffu, ss1, 2);
    if (gc == 0) {
        rs[rm][warp >> 2]     = ss0;
        rs[rm + 8][warp >> 2] = ss1;
    }
    __syncthreads();
    float r0 = rsqrtf((rs[rm][0] + rs[rm][1]) * (1.f / 64.f) + 1e-6f);
    float r1 = rsqrtf((rs[rm + 8][0] + rs[rm + 8][1]) * (1.f / 64.f) + 1e-6f);

    const size_t ob = (row0)*1024 + (size_t)(hk * 4 + h) * 64;
    #pragma unroll
    for (int nt = 0; nt < 4; nt++) {
        int cc = wn + nt * 8 + gc * 2;
        float gw0 = gnw[cc], gw1 = gnw[cc + 1];
        *(float2*)&g_oattn[ob + (size_t)rm * 1024 + cc] =
            make_float2(f2tff(acc[nt][0] * r0 * gw0), f2tff(acc[nt][1] * r0 * gw1));
        *(float2*)&g_oattn[ob + (size_t)(rm + 8) * 1024 + cc] =
            make_float2(f2tff(acc[nt][2] * r1 * gw0), f2tff(acc[nt][3] * r1 * gw1));
    }
}

// ---------------- launch -----------------------------------------------------
extern "C" void kernel_launch(void* const* d_in, const int* in_sizes, int n_in,
                              void* d_out, int out_size) {
    const float* hs  = (const float*)d_in[0];
    const float* Wq  = (const float*)d_in[1];
    const float* Wk  = (const float*)d_in[2];
    const float* Wv  = (const float*)d_in[3];
    const float* Wo  = (const float*)d_in[4];
    const float* Wg1 = (const float*)d_in[5];
    const float* Wg2 = (const float*)d_in[6];
    const float* bg2 = (const float*)d_in[7];
    const float* gnw = (const float*)d_in[8];
    float* out = (float*)d_out;

    float *phst, *pq, *pkv, *poattn, *pwkv, *pwq, *pwo;
    cudaGetSymbolAddress((void**)&phst,   g_hst);
    cudaGetSymbolAddress((void**)&pq,     g_q);
    cudaGetSymbolAddress((void**)&pkv,    g_kv);
    cudaGetSymbolAddress((void**)&poattn, g_oattn);
    cudaGetSymbolAddress((void**)&pwkv,   g_Wkv);
    cudaGetSymbolAddress((void**)&pwq,    g_Wq);
    cudaGetSymbolAddress((void**)&pwo,    g_Wo);

    cudaFuncSetAttribute(phaseC_kernel,
                         cudaFuncAttributeMaxDynamicSharedMemorySize,
                         4 * 64 * PC_LD * 4);
    cudaFuncSetAttribute(mma_gemm,
                         cudaFuncAttributeMaxDynamicSharedMemorySize,
                         GSMEM_WORDS * 4);
    const int gsmem = GSMEM_WORDS * 4;

    // prep: tf32-round inputs/weights
    prep_w<<<(HID * QCOLS) / 256, 256>>>(Wq, Wk, Wv, Wo);
    conv_hs<<<(MROWS * HID / 4) / 256, 256>>>(hs);
    // fused gate (fp32 direct from hs)
    gate_fused<<<MROWS / 32, 256>>>(hs, Wg1, Wg2, bg2);

    // q = relu(hs @ Wq)
    mma_gemm<<<dim3(QCOLS / 128, MROWS / 128), 256, gsmem>>>(phst, pwq, pq, MROWS, QCOLS, HID, QCOLS);
    // kv = [relu(hs @ Wk) | hs @ Wv]
    mma_gemm<<<dim3(KVCOLS / 128, MROWS / 128), 256, gsmem>>>(phst, pwkv, pkv, MROWS, KVCOLS, HID, 256);

    // chunked GLA
    phaseA_kernel<<<8 * NCHUNK, 64>>>();
    phaseB_kernel<<<64, 128>>>();
    phaseC_kernel<<<8 * 4 * NCHUNK, 256, 4 * 64 * PC_LD * 4>>>(gnw);

    // out = oattn @ Wo
    mma_gemm<<<dim3(HID / 128, MROWS / 128), 256, gsmem>>>(poattn, pwo, out, MROWS, HID, QCOLS, 0);
}

// round 9
// speedup vs baseline: 1.2155x; 1.2155x over previous
#include <cuda_runtime.h>
#include <math.h>

#define BB   2
#define TT   2048
#define HID  1024
#define HH   16
#define HKV  4
#define MROWS  (BB*TT)          // 4096
#define NQKV   1536             // q(1024) | k(256) | v(256)
#define QCOLS  1024
#define NCHUNK 32               // T / 64

// ---------------- scratch (device globals; no allocation) ------------------
__device__ float g_hst[MROWS * HID];       // hs rounded to tf32
__device__ float g_qkv[MROWS * NQKV];      // [relu(q) | relu(k)->ke | v]
__device__ float g_lg[MROWS * 256];        // log decay -> then be=exp(b)*0.125
__device__ float g_oattn[MROWS * QCOLS];   // normed attention out (tf32-rounded)
__device__ float g_Wqkv[HID * NQKV];       // [Wq|Wk|Wv] tf32-rounded
__device__ float g_Wo[QCOLS * HID];        // Wo tf32-rounded
__device__ float g_S[8 * NCHUNK * 64 * 64];// per-chunk entering states
__device__ float g_dl[8 * NCHUNK * 64];    // exp(b_last)

// ---------------- tf32 mma helpers -----------------------------------------
__device__ __forceinline__ unsigned f2tf(float x) {
    unsigned r; asm("cvt.rna.tf32.f32 %0, %1;" : "=r"(r) : "f"(x)); return r;
}
__device__ __forceinline__ float f2tff(float x) {
    return __uint_as_float(f2tf(x));
}
__device__ __forceinline__ void mma_tf32(float* c, const unsigned* a,
                                         unsigned b0, unsigned b1) {
    asm volatile(
        "mma.sync.aligned.m16n8k8.row.col.f32.tf32.tf32.f32 "
        "{%0,%1,%2,%3},{%4,%5,%6,%7},{%8,%9},{%0,%1,%2,%3};"
        : "+f"(c[0]), "+f"(c[1]), "+f"(c[2]), "+f"(c[3])
        : "r"(a[0]), "r"(a[1]), "r"(a[2]), "r"(a[3]), "r"(b0), "r"(b1));
}
__device__ __forceinline__ void cp16(void* smem, const void* g) {
    unsigned s = (unsigned)__cvta_generic_to_shared(smem);
    asm volatile("cp.async.cg.shared.global [%0], [%1], 16;" :: "r"(s), "l"(g) : "memory");
}
__device__ __forceinline__ void cp_commit() {
    asm volatile("cp.async.commit_group;" ::: "memory");
}

// ---------------- cp.async tf32 GEMM: C = act(A @ B), inputs pre-rounded ---
// BM=128, BN=128, BK=32, 3-stage cp.async ring, 256 threads (8 warps 4x2).
#define GLDA 36
#define GLDB 136
#define GSMEM_WORDS (3 * (128 * GLDA + 32 * GLDB))

__global__ void __launch_bounds__(256, 2) mma_gemm(const float* __restrict__ A,
                                                   const float* __restrict__ B,
                                                   float* __restrict__ C,
                                                   int M, int N, int K,
                                                   int relu_limit) {
    extern __shared__ unsigned sm[];
    unsigned (*As)[128][GLDA] = (unsigned(*)[128][GLDA])sm;
    unsigned (*Bs)[32][GLDB]  = (unsigned(*)[32][GLDB])(sm + 3 * 128 * GLDA);

    const int tid  = threadIdx.x;
    const int lane = tid & 31;
    const int warp = tid >> 5;
    const int row0 = blockIdx.y * 128;
    const int col0 = blockIdx.x * 128;
    const int wm = (warp & 3) * 32;
    const int wn = (warp >> 2) * 64;
    const int gr = lane >> 2, gc = lane & 3;

    float acc[2][8][4];
    #pragma unroll
    for (int i = 0; i < 2; i++)
        #pragma unroll
        for (int j = 0; j < 8; j++)
            #pragma unroll
            for (int l = 0; l < 4; l++) acc[i][j][l] = 0.f;

    auto CPA = [&](int kt, int st) {
        const float* ab = A + (size_t)row0 * K + kt * 32;
        #pragma unroll
        for (int i = 0; i < 4; i++) {
            int ch = tid + i * 256;          // 1024 chunks: 128 rows x 8 float4
            int r = ch >> 3, cc = (ch & 7) * 4;
            cp16(&As[st][r][cc], ab + (size_t)r * K + cc);
        }
        const float* bb = B + (size_t)kt * 32 * N + col0;
        #pragma unroll
        for (int i = 0; i < 4; i++) {
            int ch = tid + i * 256;          // 1024 chunks: 32 k x 32 float4
            int kk = ch >> 5, nn = (ch & 31) * 4;
            cp16(&Bs[st][kk][nn], bb + (size_t)kk * N + nn);
        }
        cp_commit();
    };

    auto COMP = [&](int st) {
        #pragma unroll
        for (int ks = 0; ks < 4; ks++) {
            int cb = ks * 8 + gc;
            unsigned a[2][4];
            #pragma unroll
            for (int mt = 0; mt < 2; mt++) {
                int r = wm + mt * 16 + gr;
                a[mt][0] = As[st][r][cb];
                a[mt][1] = As[st][r + 8][cb];
                a[mt][2] = As[st][r][cb + 4];
                a[mt][3] = As[st][r + 8][cb + 4];
            }
            #pragma unroll
            for (int nt = 0; nt < 8; nt++) {
                int nc = wn + nt * 8 + gr;
                unsigned b0 = Bs[st][cb][nc];
                unsigned b1 = Bs[st][cb + 4][nc];
                mma_tf32(acc[0][nt], a[0], b0, b1);
                mma_tf32(acc[1][nt], a[1], b0, b1);
            }
        }
    };

    const int NT = K / 32;
    CPA(0, 0); CPA(1, 1);
    for (int kt = 0; kt < NT; kt++) {
        if (kt + 1 < NT) {
            asm volatile("cp.async.wait_group 1;" ::: "memory");
        } else {
            asm volatile("cp.async.wait_group 0;" ::: "memory");
        }
        __syncthreads();
        if (kt + 2 < NT) CPA(kt + 2, (kt + 2) % 3);
        COMP(kt % 3);
    }

    #pragma unroll
    for (int mt = 0; mt < 2; mt++) {
        #pragma unroll
        for (int nt = 0; nt < 8; nt++) {
            int r  = row0 + wm + mt * 16 + gr;
            int cc = col0 + wn + nt * 8 + gc * 2;
            float v0 = acc[mt][nt][0], v1 = acc[mt][nt][1];
            float v2 = acc[mt][nt][2], v3 = acc[mt][nt][3];
            if (cc < relu_limit) {
                v0 = fmaxf(v0, 0.f); v1 = fmaxf(v1, 0.f);
                v2 = fmaxf(v2, 0.f); v3 = fmaxf(v3, 0.f);
            }
            *(float2*)&C[(size_t)r * N + cc]       = make_float2(v0, v1);
            *(float2*)&C[(size_t)(r + 8) * N + cc] = make_float2(v2, v3);
        }
    }
}

// ---------------- prep: round weights/activations to tf32 ------------------
__global__ void prep_w(const float* __restrict__ Wq, const float* __restrict__ Wk,
                       const float* __restrict__ Wv, const float* __restrict__ Wo) {
    int i = blockIdx.x * 256 + threadIdx.x;   // over 1.5M
    {
        int k = i / NQKV, n = i % NQKV;
        float w = (n < 1024) ? Wq[k * 1024 + n]
                : (n < 1280) ? Wk[k * 256 + n - 1024]
                             : Wv[k * 256 + n - 1280];
        g_Wqkv[i] = f2tff(w);
    }
    if (i < QCOLS * HID) g_Wo[i] = f2tff(Wo[i]);
}
__global__ void conv_hs(const float* __restrict__ hs) {
    int i = blockIdx.x * 256 + threadIdx.x;   // over 1M float4
    float4 v = ((const float4*)hs)[i];
    ((float4*)g_hst)[i] = make_float4(f2tff(v.x), f2tff(v.y), f2tff(v.z), f2tff(v.w));
}

// ---------------- fused gate: lg = logsigmoid((hs@Wg1)@Wg2 + b)/16 ---------
__global__ void __launch_bounds__(256) gate_fused(const float* __restrict__ hs,
                                                  const float* __restrict__ Wg1,
                                                  const float* __restrict__ Wg2,
                                                  const float* __restrict__ bg2) {
    __shared__ float hs_s[32][128];
    __shared__ float w1_s[128][16];
    __shared__ float glow_s[32][16];
    __shared__ float w2_s[16][256];

    const int tid = threadIdx.x;
    const int row0 = blockIdx.x * 32;
    const int rowA = tid >> 4;
    const int col  = tid & 15;

    #pragma unroll
    for (int i = tid; i < 4096; i += 256)
        w2_s[i >> 8][i & 255] = Wg2[i];

    float acc0 = 0.f, acc1 = 0.f;
    for (int kt = 0; kt < 8; kt++) {
        __syncthreads();
        #pragma unroll
        for (int i = 0; i < 4; i++) {
            int ch = tid + i * 256;
            int r = ch >> 5, cc = (ch & 31) * 4;
            *(float4*)&hs_s[r][cc] = *(const float4*)&hs[(size_t)(row0 + r) * HID + kt * 128 + cc];
        }
        #pragma unroll
        for (int i = 0; i < 2; i++) {
            int ch = tid + i * 256;
            int kk = ch >> 2, cc = (ch & 3) * 4;
            *(float4*)&w1_s[kk][cc] = *(const float4*)&Wg1[(size_t)(kt * 128 + kk) * 16 + cc];
        }
        __syncthreads();
        #pragma unroll 8
        for (int k = 0; k < 128; k++) {
            float w = w1_s[k][col];
            acc0 = fmaf(hs_s[rowA][k], w, acc0);
            acc1 = fmaf(hs_s[rowA + 16][k], w, acc1);
        }
    }
    glow_s[rowA][col]      = acc0;
    glow_s[rowA + 16][col] = acc1;
    __syncthreads();

    const int c = tid;
    const float bias = bg2[c];
    #pragma unroll 4
    for (int r = 0; r < 32; r++) {
        float x = bias;
        #pragma unroll
        for (int j = 0; j < 16; j++) x = fmaf(glow_s[r][j], w2_s[j][c], x);
        float ls = fminf(x, 0.f) - log1pf(__expf(-fabsf(x)));
        g_lg[(size_t)(row0 + r) * 256 + c] = ls * 0.0625f;
    }
}

// ---------------- Phase A: cumsum; be=exp(b)/8 in place; scale k -----------
// MLP-unrolled: batch 8 independent loads before the serial adds.
__global__ void __launch_bounds__(64) phaseA_kernel() {
    const int c   = blockIdx.x & 31;
    const int grp = blockIdx.x >> 5;
    const int b = grp >> 2, hk = grp & 3;
    const int d = threadIdx.x;
    float bacc = 0.f;
    const size_t row0 = (size_t)b * TT + c * 64;
    for (int t0 = 0; t0 < 64; t0 += 8) {
        float lg8[8], kv8[8];
        #pragma unroll
        for (int i = 0; i < 8; i++)
            lg8[i] = g_lg[(row0 + t0 + i) * 256 + hk * 64 + d];
        #pragma unroll
        for (int i = 0; i < 8; i++)
            kv8[i] = g_qkv[(row0 + t0 + i) * NQKV + 1024 + hk * 64 + d];
        #pragma unroll
        for (int i = 0; i < 8; i++) {
            bacc += lg8[i];
            g_lg[(row0 + t0 + i) * 256 + hk * 64 + d] = __expf(bacc) * 0.125f;
            g_qkv[(row0 + t0 + i) * NQKV + 1024 + hk * 64 + d] = kv8[i] * __expf(-bacc);
        }
    }
    g_dl[(grp * 32 + c) * 64 + d] = __expf(bacc);
}

// ---------------- Phase B: propagate states (cp.async double-buffered) -----
__global__ void __launch_bounds__(128) phaseB_kernel() {
    const int grp = blockIdx.x >> 3;
    const int vc  = blockIdx.x & 7;
    const int b = grp >> 2, hk = grp & 3;
    const int tid = threadIdx.x;
    const int v  = tid & 7;
    const int kg = tid >> 3;
    __shared__ __align__(16) float ke_s[2][64][64];
    __shared__ __align__(16) float v_s[2][64][8];
    float S0 = 0.f, S1 = 0.f, S2 = 0.f, S3 = 0.f;

    const size_t kbase = 1024 + hk * 64;
    const size_t vbase = 1280 + hk * 64 + vc * 8;

    auto ISSUE = [&](int c, int st) {
        const size_t row0 = (size_t)b * TT + c * 64;
        #pragma unroll
        for (int i = 0; i < 8; i++) {
            int idx = tid + i * 128;         // 1024 float4: 64 rows x 16
            int t = idx >> 4, dq = idx & 15;
            cp16(&ke_s[st][t][dq * 4], &g_qkv[(row0 + t) * NQKV + kbase + dq * 4]);
        }
        {
            int t = tid >> 1, q4 = tid & 1;  // 128 float4: 64 rows x 2
            cp16(&v_s[st][t][q4 * 4], &g_qkv[(row0 + t) * NQKV + vbase + q4 * 4]);
        }
        cp_commit();
    };

    ISSUE(0, 0);

    for (int c = 0; c < NCHUNK; c++) {
        if (c + 1 < NCHUNK) {
            ISSUE(c + 1, (c + 1) & 1);
            asm volatile("cp.async.wait_group 1;" ::: "memory");
        } else {
            asm volatile("cp.async.wait_group 0;" ::: "memory");
        }
        __syncthreads();

        const int st = c & 1;
        const size_t sb_ = ((size_t)(grp * 32 + c) * 64 + kg * 4) * 64 + vc * 8 + v;
        g_S[sb_]       = S0;
        g_S[sb_ + 64]  = S1;
        g_S[sb_ + 128] = S2;
        g_S[sb_ + 192] = S3;

        #pragma unroll 4
        for (int t = 0; t < 64; t++) {
            const float4 kk = ((const float4*)ke_s[st][t])[kg];
            const float  vv = v_s[st][t][v];
            S0 = fmaf(kk.x, vv, S0);
            S1 = fmaf(kk.y, vv, S1);
            S2 = fmaf(kk.z, vv, S2);
            S3 = fmaf(kk.w, vv, S3);
        }
        const float4 dl4 = *(const float4*)&g_dl[(grp * 32 + c) * 64 + kg * 4];
        S0 *= dl4.x; S1 *= dl4.y; S2 *= dl4.z; S3 *= dl4.w;
        __syncthreads();
    }
}

// ---------------- Phase C: tensor-core intra-chunk + inter + RMSNorm -------
#define PC_LD 65
__global__ void __launch_bounds__(256) phaseC_kernel(const float* __restrict__ gnw) {
    extern __shared__ unsigned smc[];
    unsigned* qe  = smc;
    unsigned* keT = smc + 64 * PC_LD;
    unsigned* vs  = smc + 2 * 64 * PC_LD;
    unsigned* Ss  = smc + 3 * 64 * PC_LD;
    __shared__ float rs[64][2];

    const int c   = blockIdx.x & 31;
    const int h   = (blockIdx.x >> 5) & 3;
    const int grp = blockIdx.x >> 7;
    const int b = grp >> 2, hk = grp & 3;
    const int tid  = threadIdx.x;
    const int lane = tid & 31;
    const int warp = tid >> 5;
    const int wm = (warp & 3) * 16;
    const int wn = (warp >> 2) * 32;
    const int gr = lane >> 2, gc = lane & 3;
    const size_t row0 = (size_t)b * TT + c * 64;

    for (int i = tid; i < 4096; i += 256) {
        int t = i >> 6, d = i & 63;
        float qv = g_qkv[(row0 + t) * NQKV + hk * 256 + h * 64 + d]
                 * g_lg[(row0 + t) * 256 + hk * 64 + d];
        qe [t * PC_LD + d] = f2tf(qv);
        keT[d * PC_LD + t] = f2tf(g_qkv[(row0 + t) * NQKV + 1024 + hk * 64 + d]);
        vs [t * PC_LD + d] = f2tf(g_qkv[(row0 + t) * NQKV + 1280 + hk * 64 + d]);
        Ss [t * PC_LD + d] = f2tf(g_S[((size_t)(grp * 32 + c) * 64 + t) * 64 + d]);
    }
    __syncthreads();

    float accA[4][4];
    #pragma unroll
    for (int j = 0; j < 4; j++)
        #pragma unroll
        for (int l = 0; l < 4; l++) accA[j][l] = 0.f;
    const int rm = wm + gr;
    #pragma unroll
    for (int ks = 0; ks < 8; ks++) {
        int cb = ks * 8 + gc;
        unsigned a[4];
        a[0] = qe[rm * PC_LD + cb];
        a[1] = qe[(rm + 8) * PC_LD + cb];
        a[2] = qe[rm * PC_LD + cb + 4];
        a[3] = qe[(rm + 8) * PC_LD + cb + 4];
        #pragma unroll
        for (int nt = 0; nt < 4; nt++) {
            int nc = wn + nt * 8 + gr;
            unsigned b0 = keT[cb * PC_LD + nc];
            unsigned b1 = keT[(cb + 4) * PC_LD + nc];
            mma_tf32(accA[nt], a, b0, b1);
        }
    }
    __syncthreads();
    #pragma unroll
    for (int nt = 0; nt < 4; nt++) {
        int s0 = wn + nt * 8 + gc * 2;
        keT[rm * PC_LD + s0]           = f2tf(s0     <= rm     ? accA[nt][0] : 0.f);
        keT[rm * PC_LD + s0 + 1]       = f2tf(s0 + 1 <= rm     ? accA[nt][1] : 0.f);
        keT[(rm + 8) * PC_LD + s0]     = f2tf(s0     <= rm + 8 ? accA[nt][2] : 0.f);
        keT[(rm + 8) * PC_LD + s0 + 1] = f2tf(s0 + 1 <= rm + 8 ? accA[nt][3] : 0.f);
    }
    __syncthreads();

    float acc[4][4];
    #pragma unroll
    for (int j = 0; j < 4; j++)
        #pragma unroll
        for (int l = 0; l < 4; l++) acc[j][l] = 0.f;
    #pragma unroll
    for (int ks = 0; ks < 8; ks++) {
        int cb = ks * 8 + gc;
        unsigned a[4];
        a[0] = keT[rm * PC_LD + cb];
        a[1] = keT[(rm + 8) * PC_LD + cb];
        a[2] = keT[rm * PC_LD + cb + 4];
        a[3] = keT[(rm + 8) * PC_LD + cb + 4];
        #pragma unroll
        for (int nt = 0; nt < 4; nt++) {
            int nc = wn + nt * 8 + gr;
            unsigned b0 = vs[cb * PC_LD + nc];
            unsigned b1 = vs[(cb + 4) * PC_LD + nc];
            mma_tf32(acc[nt], a, b0, b1);
        }
    }
    #pragma unroll
    for (int ks = 0; ks < 8; ks++) {
        int cb = ks * 8 + gc;
        unsigned a[4];
        a[0] = qe[rm * PC_LD + cb];
        a[1] = qe[(rm + 8) * PC_LD + cb];
        a[2] = qe[rm * PC_LD + cb + 4];
        a[3] = qe[(rm + 8) * PC_LD + cb + 4];
        #pragma unroll
        for (int nt = 0; nt < 4; nt++) {
            int nc = wn + nt * 8 + gr;
            unsigned b0 = Ss[cb * PC_LD + nc];
            unsigned b1 = Ss[(cb + 4) * PC_LD + nc];
            mma_tf32(acc[nt], a, b0, b1);
        }
    }

    float ss0 = 0.f, ss1 = 0.f;
    #pragma unroll
    for (int nt = 0; nt < 4; nt++) {
        ss0 += acc[nt][0] * acc[nt][0] + acc[nt][1] * acc[nt][1];
        ss1 += acc[nt][2] * acc[nt][2] + acc[nt][3] * acc[nt][3];
    }
    ss0 += __shfl_xor_sync(0xffffffffu, ss0, 1);
    ss0 += __shfl_xor_sync(0xffffffffu, ss0, 2);
    ss1 += __shfl_xor_sync(0xffffffffu, ss1, 1);
    ss1 += __shfl_xor_sync(0xffffffffu, ss1, 2);
    if (gc == 0) {
        rs[rm][warp >> 2]     = ss0;
        rs[rm + 8][warp >> 2] = ss1;
    }
    __syncthreads();
    float r0 = rsqrtf((rs[rm][0] + rs[rm][1]) * (1.f / 64.f) + 1e-6f);
    float r1 = rsqrtf((rs[rm + 8][0] + rs[rm + 8][1]) * (1.f / 64.f) + 1e-6f);

    const size_t ob = (row0)*1024 + (size_t)(hk * 4 + h) * 64;
    #pragma unroll
    for (int nt = 0; nt < 4; nt++) {
        int cc = wn + nt * 8 + gc * 2;
        float gw0 = gnw[cc], gw1 = gnw[cc + 1];
        *(float2*)&g_oattn[ob + (size_t)rm * 1024 + cc] =
            make_float2(f2tff(acc[nt][0] * r0 * gw0), f2tff(acc[nt][1] * r0 * gw1));
        *(float2*)&g_oattn[ob + (size_t)(rm + 8) * 1024 + cc] =
            make_float2(f2tff(acc[nt][2] * r1 * gw0), f2tff(acc[nt][3] * r1 * gw1));
    }
}

// ---------------- launch -----------------------------------------------------
extern "C" void kernel_launch(void* const* d_in, const int* in_sizes, int n_in,
                              void* d_out, int out_size) {
    const float* hs  = (const float*)d_in[0];
    const float* Wq  = (const float*)d_in[1];
    const float* Wk  = (const float*)d_in[2];
    const float* Wv  = (const float*)d_in[3];
    const float* Wo  = (const float*)d_in[4];
    const float* Wg1 = (const float*)d_in[5];
    const float* Wg2 = (const float*)d_in[6];
    const float* bg2 = (const float*)d_in[7];
    const float* gnw = (const float*)d_in[8];
    float* out = (float*)d_out;

    float *phst, *pqkv, *poattn, *pwqkv, *pwo;
    cudaGetSymbolAddress((void**)&phst,   g_hst);
    cudaGetSymbolAddress((void**)&pqkv,   g_qkv);
    cudaGetSymbolAddress((void**)&poattn, g_oattn);
    cudaGetSymbolAddress((void**)&pwqkv,  g_Wqkv);
    cudaGetSymbolAddress((void**)&pwo,    g_Wo);

    cudaFuncSetAttribute(phaseC_kernel,
                         cudaFuncAttributeMaxDynamicSharedMemorySize,
                         4 * 64 * PC_LD * 4);
    cudaFuncSetAttribute(mma_gemm,
                         cudaFuncAttributeMaxDynamicSharedMemorySize,
                         GSMEM_WORDS * 4);
    const int gsmem = GSMEM_WORDS * 4;

    // prep: tf32-round inputs/weights
    prep_w<<<(HID * NQKV) / 256, 256>>>(Wq, Wk, Wv, Wo);
    conv_hs<<<(MROWS * HID / 4) / 256, 256>>>(hs);
    // fused gate (fp32 direct from hs)
    gate_fused<<<MROWS / 32, 256>>>(hs, Wg1, Wg2, bg2);

    // qkv = [relu(hs@Wq) | relu(hs@Wk) | hs@Wv] (one merged GEMM)
    mma_gemm<<<dim3(NQKV / 128, MROWS / 128), 256, gsmem>>>(phst, pwqkv, pqkv,
                                                            MROWS, NQKV, HID, 1280);

    // chunked GLA
    phaseA_kernel<<<8 * NCHUNK, 64>>>();
    phaseB_kernel<<<64, 128>>>();
    phaseC_kernel<<<8 * 4 * NCHUNK, 256, 4 * 64 * PC_LD * 4>>>(gnw);

    // out = oattn @ Wo
    mma_gemm<<<dim3(HID / 128, MROWS / 128), 256, gsmem>>>(poattn, pwo, out,
                                                           MROWS, HID, QCOLS, 0);
}

// round 10
// speedup vs baseline: 1.3574x; 1.1168x over previous
#include <cuda_runtime.h>
#include <math.h>

#define BB   2
#define TT   2048
#define HID  1024
#define HH   16
#define HKV  4
#define MROWS  (BB*TT)          // 4096
#define NQKV   1536             // q(1024) | k(256) | v(256)
#define QCOLS  1024
#define NCHUNK 32               // T / 64
#define KT32   32               // K/32 for both GEMMs (K=1024)

// ---------------- scratch (device globals; no allocation) ------------------
__device__ float g_hstP[MROWS * HID];      // hs, tf32, fragment-major permuted
__device__ float g_qkv[MROWS * NQKV];      // [relu(q) | relu(k)->ke | v] row-major
__device__ float g_lg[MROWS * 256];        // log decay -> then be=exp(b)*0.125
__device__ float g_oattnP[MROWS * QCOLS];  // attention out, permuted for Wo GEMM
__device__ float g_WqkvP[HID * NQKV];      // [Wq|Wk|Wv] tf32 permuted (B layout)
__device__ float g_WoP[QCOLS * HID];       // Wo tf32 permuted (B layout)
__device__ float g_S[8 * NCHUNK * 64 * 64];// per-chunk entering states
__device__ float g_dl[8 * NCHUNK * 64];    // exp(b_last)

// ---------------- tf32 helpers ----------------------------------------------
__device__ __forceinline__ unsigned f2tf(float x) {
    unsigned r; asm("cvt.rna.tf32.f32 %0, %1;" : "=r"(r) : "f"(x)); return r;
}
__device__ __forceinline__ float f2tff(float x) {
    return __uint_as_float(f2tf(x));
}
__device__ __forceinline__ void mma_tf32(float* c, const unsigned* a,
                                         unsigned b0, unsigned b1) {
    asm volatile(
        "mma.sync.aligned.m16n8k8.row.col.f32.tf32.tf32.f32 "
        "{%0,%1,%2,%3},{%4,%5,%6,%7},{%8,%9},{%0,%1,%2,%3};"
        : "+f"(c[0]), "+f"(c[1]), "+f"(c[2]), "+f"(c[3])
        : "r"(a[0]), "r"(a[1]), "r"(a[2]), "r"(a[3]), "r"(b0), "r"(b1));
}
__device__ __forceinline__ void cp16(void* smem, const void* g) {
    unsigned s = (unsigned)__cvta_generic_to_shared(smem);
    asm volatile("cp.async.cg.shared.global [%0], [%1], 16;" :: "r"(s), "l"(g) : "memory");
}
__device__ __forceinline__ void cp_commit() {
    asm volatile("cp.async.commit_group;" ::: "memory");
}

// A-permuted index: element (r, c) of a row-major [M,1024] matrix.
// Tile (bm=r/128, kt=c/32); in-tile: ks(4) rblk(8) gr(8) gc(4) v(4),
// v = w*2 + rb  with rb = +8-row flag, w = +4-col flag.
__device__ __forceinline__ size_t aperm_idx(int r, int c) {
    int bm = r >> 7, rin = r & 127;
    int kt = c >> 5, cin = c & 31;
    int ks = cin >> 3, c8 = cin & 7;
    int gcn = c8 & 3, w = c8 >> 2;
    int rblk = rin >> 4, r16 = rin & 15;
    int grr = r16 & 7, rb = r16 >> 3;
    return ((size_t)(bm * KT32 + kt) << 12) +
           (size_t)(ks * 1024 + rblk * 128 + grr * 16 + gcn * 4 + w * 2 + rb);
}

// ---------------- fragment-major tf32 GEMM: C = act(A @ B) -----------------
// BM=128, BN=128, BK=32, K=1024. 3-stage cp.async ring, 256 threads (8 warps).
// A/B operands pre-permuted: tile stages are contiguous 16KB blocks.
#define GSMEM_WORDS (3 * 2 * 4096)

__global__ void __launch_bounds__(256, 2) mma_gemm(const float* __restrict__ Ap,
                                                   const float* __restrict__ Bp,
                                                   float* __restrict__ C,
                                                   int N, int relu_limit) {
    extern __shared__ unsigned sm[];
    unsigned (*As)[4096] = (unsigned(*)[4096])sm;
    unsigned (*Bs)[4096] = (unsigned(*)[4096])(sm + 3 * 4096);

    const int tid  = threadIdx.x;
    const int lane = tid & 31;
    const int warp = tid >> 5;
    const int row0 = blockIdx.y * 128;
    const int col0 = blockIdx.x * 128;
    const int wmt = (warp & 3) * 2;        // rblk base (2 per warp)
    const int wn  = (warp >> 2) * 64;
    const int gr = lane >> 2, gc = lane & 3;

    float acc[2][8][4];
    #pragma unroll
    for (int i = 0; i < 2; i++)
        #pragma unroll
        for (int j = 0; j < 8; j++)
            #pragma unroll
            for (int l = 0; l < 4; l++) acc[i][j][l] = 0.f;

    const float* abase = Ap + ((size_t)blockIdx.y * KT32 << 12);
    const float* bbase = Bp + ((size_t)blockIdx.x * KT32 << 12);

    auto CPA = [&](int kt, int st) {
        const float* at = abase + ((size_t)kt << 12);
        const float* bt = bbase + ((size_t)kt << 12);
        #pragma unroll
        for (int i = 0; i < 4; i++) {
            int ch = tid + i * 256;                  // 1024 16B chunks
            cp16(&As[st][ch * 4], at + ch * 4);
        }
        #pragma unroll
        for (int i = 0; i < 4; i++) {
            int ch = tid + i * 256;
            cp16(&Bs[st][ch * 4], bt + ch * 4);
        }
        cp_commit();
    };

    auto COMP = [&](int st) {
        #pragma unroll
        for (int ks = 0; ks < 4; ks++) {
            unsigned a[2][4];
            #pragma unroll
            for (int mt = 0; mt < 2; mt++) {
                const uint4 av = *(const uint4*)&As[st][ks * 1024 + (wmt + mt) * 128 + gr * 16 + gc * 4];
                a[mt][0] = av.x; a[mt][1] = av.y; a[mt][2] = av.z; a[mt][3] = av.w;
            }
            #pragma unroll
            for (int nt = 0; nt < 8; nt++) {
                int nc = wn + nt * 8 + gr;
                const uint2 bv = *(const uint2*)&Bs[st][ks * 1024 + nc * 8 + gc * 2];
                mma_tf32(acc[0][nt], a[0], bv.x, bv.y);
                mma_tf32(acc[1][nt], a[1], bv.x, bv.y);
            }
        }
    };

    CPA(0, 0); CPA(1, 1);
    for (int kt = 0; kt < KT32; kt++) {
        if (kt + 1 < KT32) {
            asm volatile("cp.async.wait_group 1;" ::: "memory");
        } else {
            asm volatile("cp.async.wait_group 0;" ::: "memory");
        }
        __syncthreads();
        if (kt + 2 < KT32) CPA(kt + 2, (kt + 2) % 3);
        COMP(kt % 3);
    }

    #pragma unroll
    for (int mt = 0; mt < 2; mt++) {
        #pragma unroll
        for (int nt = 0; nt < 8; nt++) {
            int r  = row0 + (wmt + mt) * 16 + gr;
            int cc = col0 + wn + nt * 8 + gc * 2;
            float v0 = acc[mt][nt][0], v1 = acc[mt][nt][1];
            float v2 = acc[mt][nt][2], v3 = acc[mt][nt][3];
            if (cc < relu_limit) {
                v0 = fmaxf(v0, 0.f); v1 = fmaxf(v1, 0.f);
                v2 = fmaxf(v2, 0.f); v3 = fmaxf(v3, 0.f);
            }
            *(float2*)&C[(size_t)r * N + cc]       = make_float2(v0, v1);
            *(float2*)&C[(size_t)(r + 8) * N + cc] = make_float2(v2, v3);
        }
    }
}

// ---------------- prep: permute+round weights (B layout) -------------------
// B layout per tile (kt,bn): [ks(4)][nn(128)][gc(4)][w(2)];
// element = W[kt*32+ks*8+gc+w*4][bn*128+nn]. One thread per float2 (w pair).
__global__ void prep_w(const float* __restrict__ Wq, const float* __restrict__ Wk,
                       const float* __restrict__ Wv, const float* __restrict__ Wo) {
    int i = blockIdx.x * 256 + threadIdx.x;     // 1,310,720 float2 total
    if (i < 786432) {                           // Wqkv: N=1536, 384 tiles
        int tile = i >> 11, inner2 = i & 2047;
        int ks = inner2 >> 9, nn = (inner2 >> 2) & 127, gcn = inner2 & 3;
        int bn = tile >> 5, kt = tile & 31;
        int k0 = kt * 32 + ks * 8 + gcn;
        int n  = bn * 128 + nn;
        float w0, w1;
        if (n < 1024)      { w0 = Wq[(size_t)k0 * 1024 + n];       w1 = Wq[(size_t)(k0 + 4) * 1024 + n]; }
        else if (n < 1280) { w0 = Wk[(size_t)k0 * 256 + n - 1024]; w1 = Wk[(size_t)(k0 + 4) * 256 + n - 1024]; }
        else               { w0 = Wv[(size_t)k0 * 256 + n - 1280]; w1 = Wv[(size_t)(k0 + 4) * 256 + n - 1280]; }
        g_WqkvP[(size_t)i * 2]     = f2tff(w0);
        g_WqkvP[(size_t)i * 2 + 1] = f2tff(w1);
    } else {                                    // Wo: N=1024, 256 tiles
        int j = i - 786432;
        int tile = j >> 11, inner2 = j & 2047;
        int ks = inner2 >> 9, nn = (inner2 >> 2) & 127, gcn = inner2 & 3;
        int bn = tile >> 5, kt = tile & 31;
        int k0 = kt * 32 + ks * 8 + gcn;
        int n  = bn * 128 + nn;
        g_WoP[(size_t)j * 2]     = f2tff(Wo[(size_t)k0 * 1024 + n]);
        g_WoP[(size_t)j * 2 + 1] = f2tff(Wo[(size_t)(k0 + 4) * 1024 + n]);
    }
}

// permute+round hs into A layout. One thread per output float4 (v group).
__global__ void conv_hs(const float* __restrict__ hs) {
    int o4 = blockIdx.x * 256 + threadIdx.x;    // 1M float4
    int tile = o4 >> 10, inner4 = o4 & 1023;
    int ks = inner4 >> 8, rblk = (inner4 >> 5) & 7, grr = (inner4 >> 2) & 7, gcn = inner4 & 3;
    int bm = tile >> 5, kt = tile & 31;
    int r0 = bm * 128 + rblk * 16 + grr;
    int c0 = kt * 32 + ks * 8 + gcn;
    float4 o;
    o.x = f2tff(hs[(size_t)r0 * HID + c0]);
    o.y = f2tff(hs[(size_t)(r0 + 8) * HID + c0]);
    o.z = f2tff(hs[(size_t)r0 * HID + c0 + 4]);
    o.w = f2tff(hs[(size_t)(r0 + 8) * HID + c0 + 4]);
    ((float4*)g_hstP)[o4] = o;
}

// ---------------- fused gate: lg = logsigmoid((hs@Wg1)@Wg2 + b)/16 ---------
__global__ void __launch_bounds__(256) gate_fused(const float* __restrict__ hs,
                                                  const float* __restrict__ Wg1,
                                                  const float* __restrict__ Wg2,
                                                  const float* __restrict__ bg2) {
    __shared__ float hs_s[32][128];
    __shared__ float w1_s[128][16];
    __shared__ float glow_s[32][16];
    __shared__ float w2_s[16][256];

    const int tid = threadIdx.x;
    const int row0 = blockIdx.x * 32;
    const int rowA = tid >> 4;
    const int col  = tid & 15;

    #pragma unroll
    for (int i = tid; i < 4096; i += 256)
        w2_s[i >> 8][i & 255] = Wg2[i];

    float acc0 = 0.f, acc1 = 0.f;
    for (int kt = 0; kt < 8; kt++) {
        __syncthreads();
        #pragma unroll
        for (int i = 0; i < 4; i++) {
            int ch = tid + i * 256;
            int r = ch >> 5, cc = (ch & 31) * 4;
            *(float4*)&hs_s[r][cc] = *(const float4*)&hs[(size_t)(row0 + r) * HID + kt * 128 + cc];
        }
        #pragma unroll
        for (int i = 0; i < 2; i++) {
            int ch = tid + i * 256;
            int kk = ch >> 2, cc = (ch & 3) * 4;
            *(float4*)&w1_s[kk][cc] = *(const float4*)&Wg1[(size_t)(kt * 128 + kk) * 16 + cc];
        }
        __syncthreads();
        #pragma unroll 8
        for (int k = 0; k < 128; k++) {
            float w = w1_s[k][col];
            acc0 = fmaf(hs_s[rowA][k], w, acc0);
            acc1 = fmaf(hs_s[rowA + 16][k], w, acc1);
        }
    }
    glow_s[rowA][col]      = acc0;
    glow_s[rowA + 16][col] = acc1;
    __syncthreads();

    const int c = tid;
    const float bias = bg2[c];
    #pragma unroll 4
    for (int r = 0; r < 32; r++) {
        float x = bias;
        #pragma unroll
        for (int j = 0; j < 16; j++) x = fmaf(glow_s[r][j], w2_s[j][c], x);
        float ls = fminf(x, 0.f) - log1pf(__expf(-fabsf(x)));
        g_lg[(size_t)(row0 + r) * 256 + c] = ls * 0.0625f;
    }
}

// ---------------- Phase A: cumsum; be=exp(b)/8 in place; scale k -----------
__global__ void __launch_bounds__(64) phaseA_kernel() {
    const int c   = blockIdx.x & 31;
    const int grp = blockIdx.x >> 5;
    const int b = grp >> 2, hk = grp & 3;
    const int d = threadIdx.x;
    float bacc = 0.f;
    const size_t row0 = (size_t)b * TT + c * 64;
    for (int t0 = 0; t0 < 64; t0 += 8) {
        float lg8[8], kv8[8];
        #pragma unroll
        for (int i = 0; i < 8; i++)
            lg8[i] = g_lg[(row0 + t0 + i) * 256 + hk * 64 + d];
        #pragma unroll
        for (int i = 0; i < 8; i++)
            kv8[i] = g_qkv[(row0 + t0 + i) * NQKV + 1024 + hk * 64 + d];
        #pragma unroll
        for (int i = 0; i < 8; i++) {
            bacc += lg8[i];
            g_lg[(row0 + t0 + i) * 256 + hk * 64 + d] = __expf(bacc) * 0.125f;
            g_qkv[(row0 + t0 + i) * NQKV + 1024 + hk * 64 + d] = kv8[i] * __expf(-bacc);
        }
    }
    g_dl[(grp * 32 + c) * 64 + d] = __expf(bacc);
}

// ---------------- Phase B: propagate states (cp.async double-buffered) -----
__global__ void __launch_bounds__(128) phaseB_kernel() {
    const int grp = blockIdx.x >> 3;
    const int vc  = blockIdx.x & 7;
    const int b = grp >> 2, hk = grp & 3;
    const int tid = threadIdx.x;
    const int v  = tid & 7;
    const int kg = tid >> 3;
    __shared__ __align__(16) float ke_s[2][64][64];
    __shared__ __align__(16) float v_s[2][64][8];
    float S0 = 0.f, S1 = 0.f, S2 = 0.f, S3 = 0.f;

    const size_t kbase = 1024 + hk * 64;
    const size_t vbase = 1280 + hk * 64 + vc * 8;

    auto ISSUE = [&](int c, int st) {
        const size_t row0 = (size_t)b * TT + c * 64;
        #pragma unroll
        for (int i = 0; i < 8; i++) {
            int idx = tid + i * 128;
            int t = idx >> 4, dq = idx & 15;
            cp16(&ke_s[st][t][dq * 4], &g_qkv[(row0 + t) * NQKV + kbase + dq * 4]);
        }
        {
            int t = tid >> 1, q4 = tid & 1;
            cp16(&v_s[st][t][q4 * 4], &g_qkv[(row0 + t) * NQKV + vbase + q4 * 4]);
        }
        cp_commit();
    };

    ISSUE(0, 0);

    for (int c = 0; c < NCHUNK; c++) {
        if (c + 1 < NCHUNK) {
            ISSUE(c + 1, (c + 1) & 1);
            asm volatile("cp.async.wait_group 1;" ::: "memory");
        } else {
            asm volatile("cp.async.wait_group 0;" ::: "memory");
        }
        __syncthreads();

        const int st = c & 1;
        const size_t sb_ = ((size_t)(grp * 32 + c) * 64 + kg * 4) * 64 + vc * 8 + v;
        g_S[sb_]       = S0;
        g_S[sb_ + 64]  = S1;
        g_S[sb_ + 128] = S2;
        g_S[sb_ + 192] = S3;

        #pragma unroll 4
        for (int t = 0; t < 64; t++) {
            const float4 kk = ((const float4*)ke_s[st][t])[kg];
            const float  vv = v_s[st][t][v];
            S0 = fmaf(kk.x, vv, S0);
            S1 = fmaf(kk.y, vv, S1);
            S2 = fmaf(kk.z, vv, S2);
            S3 = fmaf(kk.w, vv, S3);
        }
        const float4 dl4 = *(const float4*)&g_dl[(grp * 32 + c) * 64 + kg * 4];
        S0 *= dl4.x; S1 *= dl4.y; S2 *= dl4.z; S3 *= dl4.w;
        __syncthreads();
    }
}

// ---------------- Phase C: tensor-core intra-chunk + inter + RMSNorm -------
#define PC_LD 65
__global__ void __launch_bounds__(256) phaseC_kernel(const float* __restrict__ gnw) {
    extern __shared__ unsigned smc[];
    unsigned* qe  = smc;
    unsigned* keT = smc + 64 * PC_LD;
    unsigned* vs  = smc + 2 * 64 * PC_LD;
    unsigned* Ss  = smc + 3 * 64 * PC_LD;
    __shared__ float rs[64][2];

    const int c   = blockIdx.x & 31;
    const int h   = (blockIdx.x >> 5) & 3;
    const int grp = blockIdx.x >> 7;
    const int b = grp >> 2, hk = grp & 3;
    const int tid  = threadIdx.x;
    const int lane = tid & 31;
    const int warp = tid >> 5;
    const int wm = (warp & 3) * 16;
    const int wn = (warp >> 2) * 32;
    const int gr = lane >> 2, gc = lane & 3;
    const size_t row0 = (size_t)b * TT + c * 64;

    for (int i = tid; i < 4096; i += 256) {
        int t = i >> 6, d = i & 63;
        float qv = g_qkv[(row0 + t) * NQKV + hk * 256 + h * 64 + d]
                 * g_lg[(row0 + t) * 256 + hk * 64 + d];
        qe [t * PC_LD + d] = f2tf(qv);
        keT[d * PC_LD + t] = f2tf(g_qkv[(row0 + t) * NQKV + 1024 + hk * 64 + d]);
        vs [t * PC_LD + d] = f2tf(g_qkv[(row0 + t) * NQKV + 1280 + hk * 64 + d]);
        Ss [t * PC_LD + d] = f2tf(g_S[((size_t)(grp * 32 + c) * 64 + t) * 64 + d]);
    }
    __syncthreads();

    float accA[4][4];
    #pragma unroll
    for (int j = 0; j < 4; j++)
        #pragma unroll
        for (int l = 0; l < 4; l++) accA[j][l] = 0.f;
    const int rm = wm + gr;
    #pragma unroll
    for (int ks = 0; ks < 8; ks++) {
        int cb = ks * 8 + gc;
        unsigned a[4];
        a[0] = qe[rm * PC_LD + cb];
        a[1] = qe[(rm + 8) * PC_LD + cb];
        a[2] = qe[rm * PC_LD + cb + 4];
        a[3] = qe[(rm + 8) * PC_LD + cb + 4];
        #pragma unroll
        for (int nt = 0; nt < 4; nt++) {
            int nc = wn + nt * 8 + gr;
            unsigned b0 = keT[cb * PC_LD + nc];
            unsigned b1 = keT[(cb + 4) * PC_LD + nc];
            mma_tf32(accA[nt], a, b0, b1);
        }
    }
    __syncthreads();
    #pragma unroll
    for (int nt = 0; nt < 4; nt++) {
        int s0 = wn + nt * 8 + gc * 2;
        keT[rm * PC_LD + s0]           = f2tf(s0     <= rm     ? accA[nt][0] : 0.f);
        keT[rm * PC_LD + s0 + 1]       = f2tf(s0 + 1 <= rm     ? accA[nt][1] : 0.f);
        keT[(rm + 8) * PC_LD + s0]     = f2tf(s0     <= rm + 8 ? accA[nt][2] : 0.f);
        keT[(rm + 8) * PC_LD + s0 + 1] = f2tf(s0 + 1 <= rm + 8 ? accA[nt][3] : 0.f);
    }
    __syncthreads();

    float acc[4][4];
    #pragma unroll
    for (int j = 0; j < 4; j++)
        #pragma unroll
        for (int l = 0; l < 4; l++) acc[j][l] = 0.f;
    #pragma unroll
    for (int ks = 0; ks < 8; ks++) {
        int cb = ks * 8 + gc;
        unsigned a[4];
        a[0] = keT[rm * PC_LD + cb];
        a[1] = keT[(rm + 8) * PC_LD + cb];
        a[2] = keT[rm * PC_LD + cb + 4];
        a[3] = keT[(rm + 8) * PC_LD + cb + 4];
        #pragma unroll
        for (int nt = 0; nt < 4; nt++) {
            int nc = wn + nt * 8 + gr;
            unsigned b0 = vs[cb * PC_LD + nc];
            unsigned b1 = vs[(cb + 4) * PC_LD + nc];
            mma_tf32(acc[nt], a, b0, b1);
        }
    }
    #pragma unroll
    for (int ks = 0; ks < 8; ks++) {
        int cb = ks * 8 + gc;
        unsigned a[4];
        a[0] = qe[rm * PC_LD + cb];
        a[1] = qe[(rm + 8) * PC_LD + cb];
        a[2] = qe[rm * PC_LD + cb + 4];
        a[3] = qe[(rm + 8) * PC_LD + cb + 4];
        #pragma unroll
        for (int nt = 0; nt < 4; nt++) {
            int nc = wn + nt * 8 + gr;
            unsigned b0 = Ss[cb * PC_LD + nc];
            unsigned b1 = Ss[(cb + 4) * PC_LD + nc];
            mma_tf32(acc[nt], a, b0, b1);
        }
    }

    float ss0 = 0.f, ss1 = 0.f;
    #pragma unroll
    for (int nt = 0; nt < 4; nt++) {
        ss0 += acc[nt][0] * acc[nt][0] + acc[nt][1] * acc[nt][1];
        ss1 += acc[nt][2] * acc[nt][2] + acc[nt][3] * acc[nt][3];
    }
    ss0 += __shfl_xor_sync(0xffffffffu, ss0, 1);
    ss0 += __shfl_xor_sync(0xffffffffu, ss0, 2);
    ss1 += __shfl_xor_sync(0xffffffffu, ss1, 1);
    ss1 += __shfl_xor_sync(0xffffffffu, ss1, 2);
    if (gc == 0) {
        rs[rm][warp >> 2]     = ss0;
        rs[rm + 8][warp >> 2] = ss1;
    }
    __syncthreads();
    float r0 = rsqrtf((rs[rm][0] + rs[rm][1]) * (1.f / 64.f) + 1e-6f);
    float r1 = rsqrtf((rs[rm + 8][0] + rs[rm + 8][1]) * (1.f / 64.f) + 1e-6f);

    // write permuted (A layout for Wo GEMM), tf32-rounded
    const int rowg = (int)row0 + rm;
    const int cbase = (hk * 4 + h) * 64;
    #pragma unroll
    for (int nt = 0; nt < 4; nt++) {
        #pragma unroll
        for (int j = 0; j < 2; j++) {
            int colg = cbase + wn + nt * 8 + gc * 2 + j;
            float gw = gnw[wn + nt * 8 + gc * 2 + j];
            g_oattnP[aperm_idx(rowg, colg)]     = f2tff(acc[nt][j]     * r0 * gw);
            g_oattnP[aperm_idx(rowg + 8, colg)] = f2tff(acc[nt][2 + j] * r1 * gw);
        }
    }
}

// ---------------- launch -----------------------------------------------------
extern "C" void kernel_launch(void* const* d_in, const int* in_sizes, int n_in,
                              void* d_out, int out_size) {
    const float* hs  = (const float*)d_in[0];
    const float* Wq  = (const float*)d_in[1];
    const float* Wk  = (const float*)d_in[2];
    const float* Wv  = (const float*)d_in[3];
    const float* Wo  = (const float*)d_in[4];
    const float* Wg1 = (const float*)d_in[5];
    const float* Wg2 = (const float*)d_in[6];
    const float* bg2 = (const float*)d_in[7];
    const float* gnw = (const float*)d_in[8];
    float* out = (float*)d_out;

    float *phstP, *pqkv, *poattnP, *pwqkvP, *pwoP;
    cudaGetSymbolAddress((void**)&phstP,   g_hstP);
    cudaGetSymbolAddress((void**)&pqkv,    g_qkv);
    cudaGetSymbolAddress((void**)&poattnP, g_oattnP);
    cudaGetSymbolAddress((void**)&pwqkvP,  g_WqkvP);
    cudaGetSymbolAddress((void**)&pwoP,    g_WoP);

    cudaFuncSetAttribute(phaseC_kernel,
                         cudaFuncAttributeMaxDynamicSharedMemorySize,
                         4 * 64 * PC_LD * 4);
    cudaFuncSetAttribute(mma_gemm,
                         cudaFuncAttributeMaxDynamicSharedMemorySize,
                         GSMEM_WORDS * 4);
    const int gsmem = GSMEM_WORDS * 4;

    // prep: permute+round inputs/weights
    prep_w<<<5120, 256>>>(Wq, Wk, Wv, Wo);
    conv_hs<<<4096, 256>>>(hs);
    // fused gate (fp32 direct from hs)
    gate_fused<<<MROWS / 32, 256>>>(hs, Wg1, Wg2, bg2);

    // qkv = [relu(hs@Wq) | relu(hs@Wk) | hs@Wv]
    mma_gemm<<<dim3(NQKV / 128, MROWS / 128), 256, gsmem>>>(phstP, pwqkvP, pqkv,
                                                            NQKV, 1280);

    // chunked GLA
    phaseA_kernel<<<8 * NCHUNK, 64>>>();
    phaseB_kernel<<<64, 128>>>();
    phaseC_kernel<<<8 * 4 * NCHUNK, 256, 4 * 64 * PC_LD * 4>>>(gnw);

    // out = oattn @ Wo
    mma_gemm<<<dim3(HID / 128, MROWS / 128), 256, gsmem>>>(poattnP, pwoP, out,
                                                           HID, 0);
}